// round 5
// baseline (speedup 1.0000x reference)
#include <cuda_runtime.h>

#define N_NODES 16384
#define N_EDGES 131072
#define F_IN 6
#define S_DIM 4
#define G_NUM 256
#define H_DIM 30
#define C1 32
#define C2 64
#define C3 32
#define EN_EDGES (N_EDGES + N_NODES)
#define K1 192          /* 30*6 wk1 + 6 bk1 + 6 root1 */
#define K2 1024         /* 30*32 wk2 + 32 bk2 + 32 root2 */

// ---------------- scratch ----------------------------------------------------
__device__ float g_H1[N_EDGES * H_DIM];
__device__ float g_H2[N_EDGES * H_DIM];
__device__ float g_P1[N_NODES * K1];
__device__ float g_P2[N_NODES * K2];
__device__ float g_X1[N_NODES * C1];
__device__ float g_XW[N_NODES * C3];
__device__ float g_ACC3[N_NODES * C3];
__device__ float g_W1[K1 * C1];
__device__ float g_W2[K2 * C2];
__device__ int g_deg[N_NODES];
__device__ int g_rowptr[N_NODES + 1];
__device__ int g_cursor[N_NODES];
__device__ int g_csr[N_EDGES];

// ---------------- packed f32x2 helpers ---------------------------------------
__device__ __forceinline__ unsigned long long pk2(float lo, float hi) {
    unsigned long long r;
    asm("mov.b64 %0, {%1, %2};" : "=l"(r) : "f"(lo), "f"(hi));
    return r;
}
__device__ __forceinline__ void upk2(unsigned long long v, float& lo, float& hi) {
    asm("mov.b64 {%0, %1}, %2;" : "=f"(lo), "=f"(hi) : "l"(v));
}
__device__ __forceinline__ unsigned long long fma2(unsigned long long a,
                                                   unsigned long long b,
                                                   unsigned long long c) {
    unsigned long long d;
    asm("fma.rn.f32x2 %0, %1, %2, %3;" : "=l"(d) : "l"(a), "l"(b), "l"(c));
    return d;
}

// ---------------- zero -------------------------------------------------------
__global__ void k_zero(float* __restrict__ out, int out_n) {
    int i = blockIdx.x * blockDim.x + threadIdx.x;
    if (i < N_NODES * C3) g_ACC3[i] = 0.f;
    if (i < N_NODES)      g_deg[i]  = 0;
    if (i < out_n)        out[i]    = 0.f;
}

// ---------------- weight assembly --------------------------------------------
__global__ void k_wasm(const float* __restrict__ e1_wk, const float* __restrict__ e1_bk,
                       const float* __restrict__ e1_root,
                       const float* __restrict__ e2_wk, const float* __restrict__ e2_bk,
                       const float* __restrict__ e2_root) {
    int i = blockIdx.x * blockDim.x + threadIdx.x;
    if (i < K1 * C1) {
        int k = i / C1, c = i % C1;
        float v;
        if (k < 180)      { int h = k / 6, f = k % 6; v = e1_wk[h * (F_IN * C1) + f * C1 + c]; }
        else if (k < 186) { int f = k - 180;          v = e1_bk[f * C1 + c]; }
        else              { int f = k - 186;          v = e1_root[f * C1 + c]; }
        g_W1[i] = v;
    }
    int j = i;
    if (j < K2 * C2) {
        int k = j / C2, c = j % C2;
        float v;
        if (k < 960)      { int h = k >> 5, c1 = k & 31; v = e2_wk[h * (C1 * C2) + c1 * C2 + c]; }
        else if (k < 992) { int c1 = k - 960;            v = e2_bk[c1 * C2 + c]; }
        else              { int c1 = k - 992;            v = e2_root[c1 * C2 + c]; }
        g_W2[j] = v;
    }
}

// ---------------- CSR build (by tgt) -----------------------------------------
__global__ void k_scan() {  // 1 block, 1024 threads, 16 elems/thread
    __shared__ int part[1024];
    int tid = threadIdx.x;
    int base = tid * 16;
    int loc[16];
    int s = 0;
    #pragma unroll
    for (int i = 0; i < 16; i++) { loc[i] = s; s += g_deg[base + i]; }
    int val = s;
    part[tid] = s;
    __syncthreads();
    for (int d = 1; d < 1024; d <<= 1) {
        int t = (tid >= d) ? part[tid - d] : 0;
        __syncthreads();
        part[tid] += t;
        __syncthreads();
    }
    int off = part[tid] - val;
    #pragma unroll
    for (int i = 0; i < 16; i++) {
        g_rowptr[base + i] = off + loc[i];
        g_cursor[base + i] = off + loc[i];
    }
    if (tid == 1023) g_rowptr[N_NODES] = off + val;
}

__global__ void k_scatter(const int* __restrict__ tgt) {
    int e = blockIdx.x * blockDim.x + threadIdx.x;
    if (e < N_EDGES) {
        int p = atomicAdd(&g_cursor[tgt[e]], 1);
        g_csr[p] = e;
    }
}

// ---------------- edge MLPs (+ tgt histogram) --------------------------------
__global__ void k_edge_mlp(const float* __restrict__ e, const int* __restrict__ tgt,
                           const float* __restrict__ w0a, const float* __restrict__ b0a,
                           const float* __restrict__ w1a, const float* __restrict__ b1a,
                           const float* __restrict__ w0b, const float* __restrict__ b0b,
                           const float* __restrict__ w1b, const float* __restrict__ b1b) {
    __shared__ float sw0[2][S_DIM * H_DIM];
    __shared__ float sb0[2][H_DIM];
    __shared__ float sw1[2][H_DIM * H_DIM];
    __shared__ float sb1[2][H_DIM];
    for (int i = threadIdx.x; i < S_DIM * H_DIM; i += blockDim.x) {
        sw0[0][i] = w0a[i]; sw0[1][i] = w0b[i];
    }
    for (int i = threadIdx.x; i < H_DIM; i += blockDim.x) {
        sb0[0][i] = b0a[i]; sb0[1][i] = b0b[i];
        sb1[0][i] = b1a[i]; sb1[1][i] = b1b[i];
    }
    for (int i = threadIdx.x; i < H_DIM * H_DIM; i += blockDim.x) {
        sw1[0][i] = w1a[i]; sw1[1][i] = w1b[i];
    }
    __syncthreads();

    int eid = blockIdx.x * blockDim.x + threadIdx.x;
    if (eid >= N_EDGES) return;
    atomicAdd(&g_deg[tgt[eid]], 1);
    float4 ev4 = *reinterpret_cast<const float4*>(e + eid * 4);
    float ev[4] = {ev4.x, ev4.y, ev4.z, ev4.w};

    #pragma unroll
    for (int set = 0; set < 2; set++) {
        float h0[H_DIM];
        #pragma unroll
        for (int j = 0; j < H_DIM; j++) {
            float a = sb0[set][j];
            #pragma unroll
            for (int s = 0; s < S_DIM; s++) a += ev[s] * sw0[set][s * H_DIM + j];
            h0[j] = fmaxf(a, 0.f);
        }
        float* dst = (set == 0 ? g_H1 : g_H2) + eid * H_DIM;
        #pragma unroll 5
        for (int j = 0; j < H_DIM; j++) {
            float a = sb1[set][j];
            #pragma unroll
            for (int k = 0; k < H_DIM; k++) a += h0[k] * sw1[set][k * H_DIM + j];
            dst[j] = fmaxf(a, 0.f);
        }
    }
}

// ---------------- P1: per-target outer-product sums (ECC1) -------------------
// P1[t, h*6+f] = sum_{e:tgt=t} h1[e,h]*x[src,f]  (h=30 row: h==1 -> Q1)
// P1[t, 186+f] = x[t,f]  (root rows)
__global__ void k_p1(const float* __restrict__ x, const int* __restrict__ src) {
    int t = (blockIdx.x * blockDim.x + threadIdx.x) >> 5;
    int lane = threadIdx.x & 31;
    if (t >= N_NODES) return;
    int rs = g_rowptr[t], re = g_rowptr[t + 1];
    float acc[6] = {0.f, 0.f, 0.f, 0.f, 0.f, 0.f};
    float hv_fix = (lane == 30) ? 1.f : 0.f;
    for (int pos = rs; pos < re; pos++) {
        int eid = g_csr[pos];
        int s = src[eid];
        float xl = (lane < 6) ? x[s * 6 + lane] : 0.f;
        float hv = (lane < 30) ? g_H1[eid * H_DIM + lane] : hv_fix;
        #pragma unroll
        for (int f = 0; f < 6; f++)
            acc[f] += hv * __shfl_sync(0xffffffffu, xl, f);
    }
    if (lane == 31) {
        #pragma unroll
        for (int f = 0; f < 6; f++) acc[f] = x[t * 6 + f];
    }
    #pragma unroll
    for (int f = 0; f < 6; f++) g_P1[t * K1 + lane * 6 + f] = acc[f];
}

// ---------------- GEMM1: X1 = relu(P1 @ W1 + bias1)  [16384x192]@[192x32] ----
// block: 128 rows x 32 cols, 256 threads, k-chunks of 32
__global__ void k_gemm1(const float* __restrict__ bias1) {
    __shared__ float sA[32 * 130];
    __shared__ float sB[32 * 32];
    int tid = threadIdx.x;
    int nb = blockIdx.x * 128;
    int tx = tid & 7;           // col group: cols tx*4..tx*4+3
    int ty = tid >> 3;          // row group: rows ty*4..ty*4+3
    unsigned long long acc2[2][4];
    #pragma unroll
    for (int p = 0; p < 2; p++)
        #pragma unroll
        for (int j = 0; j < 4; j++) acc2[p][j] = 0ull;

    for (int k0 = 0; k0 < K1; k0 += 32) {
        // load A tile (128x32) transposed into sA[k][row]
        int lrow = tid >> 3, lk4 = (tid & 7) * 4;
        #pragma unroll
        for (int j = 0; j < 4; j++) {
            int row = lrow + 32 * j;
            float4 v = *reinterpret_cast<const float4*>(&g_P1[(nb + row) * K1 + k0 + lk4]);
            sA[(lk4 + 0) * 130 + row] = v.x;
            sA[(lk4 + 1) * 130 + row] = v.y;
            sA[(lk4 + 2) * 130 + row] = v.z;
            sA[(lk4 + 3) * 130 + row] = v.w;
        }
        // load B tile (32x32)
        {
            int kr = tid >> 3, c4 = (tid & 7) * 4;
            float4 v = *reinterpret_cast<const float4*>(&g_W1[(k0 + kr) * C1 + c4]);
            *reinterpret_cast<float4*>(&sB[kr * 32 + c4]) = v;
        }
        __syncthreads();
        #pragma unroll 8
        for (int k = 0; k < 32; k++) {
            unsigned long long a0 = *reinterpret_cast<const unsigned long long*>(&sA[k * 130 + ty * 4]);
            unsigned long long a1 = *reinterpret_cast<const unsigned long long*>(&sA[k * 130 + ty * 4 + 2]);
            float4 b = *reinterpret_cast<const float4*>(&sB[k * 32 + tx * 4]);
            float bb[4] = {b.x, b.y, b.z, b.w};
            #pragma unroll
            for (int j = 0; j < 4; j++) {
                unsigned long long bp = pk2(bb[j], bb[j]);
                acc2[0][j] = fma2(a0, bp, acc2[0][j]);
                acc2[1][j] = fma2(a1, bp, acc2[1][j]);
            }
        }
        __syncthreads();
    }
    #pragma unroll
    for (int p = 0; p < 2; p++)
        #pragma unroll
        for (int j = 0; j < 4; j++) {
            float v0, v1;
            upk2(acc2[p][j], v0, v1);
            int c = tx * 4 + j;
            float bs = bias1[c];
            int r0 = nb + ty * 4 + p * 2;
            g_X1[r0 * C1 + c]       = fmaxf(v0 + bs, 0.f);
            g_X1[(r0 + 1) * C1 + c] = fmaxf(v1 + bs, 0.f);
        }
}

// ---------------- P2: per-target outer-product sums (ECC2) -------------------
// P2[t, h*32+c1] = sum_{e:tgt=t} h2[e,h]*x1[src,c1];  row30: sum x1[src]; row31: x1[t]
__global__ void k_p2(const int* __restrict__ src) {
    int t = (blockIdx.x * blockDim.x + threadIdx.x) >> 5;
    int lane = threadIdx.x & 31;
    if (t >= N_NODES) return;
    int rs = g_rowptr[t], re = g_rowptr[t + 1];
    float acc[31];
    #pragma unroll
    for (int h = 0; h < 31; h++) acc[h] = 0.f;
    for (int pos = rs; pos < re; pos++) {
        int eid = g_csr[pos];
        int s = src[eid];
        float x1v = g_X1[s * C1 + lane];
        float hl = (lane < 30) ? g_H2[eid * H_DIM + lane] : 0.f;
        #pragma unroll
        for (int h = 0; h < 30; h++)
            acc[h] += __shfl_sync(0xffffffffu, hl, h) * x1v;
        acc[30] += x1v;
    }
    #pragma unroll
    for (int h = 0; h < 31; h++)
        g_P2[t * K2 + h * 32 + lane] = acc[h];
    g_P2[t * K2 + 992 + lane] = g_X1[t * C1 + lane];
}

// ---------------- GEMM2 + fused GCN-xw ---------------------------------------
// X2 = relu(P2 @ W2 + bias2) [128x64 per block]; then XW = X2 @ gcn_W [128x32]
__global__ void k_gemm2(const float* __restrict__ bias2, const float* __restrict__ gcnW) {
    __shared__ float smu[128 * 68];          // union: (sA 32*130 + sB 32*64) | sX2 128*68
    __shared__ float sW[C2 * C3];            // gcn_W
    float* sA = smu;                          // 4160 floats
    float* sB = smu + 4160;                   // 2048 floats
    int tid = threadIdx.x;
    int nb = blockIdx.x * 128;
    for (int i = tid; i < C2 * C3; i += 256) sW[i] = gcnW[i];

    int tx = tid & 15;          // cols tx*4..+3
    int ty = tid >> 4;          // rows ty*8..+7 (4 pairs)
    unsigned long long acc2[4][4];
    #pragma unroll
    for (int p = 0; p < 4; p++)
        #pragma unroll
        for (int j = 0; j < 4; j++) acc2[p][j] = 0ull;

    for (int k0 = 0; k0 < K2; k0 += 32) {
        int lrow = tid >> 3, lk4 = (tid & 7) * 4;
        #pragma unroll
        for (int j = 0; j < 4; j++) {
            int row = lrow + 32 * j;
            float4 v = *reinterpret_cast<const float4*>(&g_P2[(nb + row) * K2 + k0 + lk4]);
            sA[(lk4 + 0) * 130 + row] = v.x;
            sA[(lk4 + 1) * 130 + row] = v.y;
            sA[(lk4 + 2) * 130 + row] = v.z;
            sA[(lk4 + 3) * 130 + row] = v.w;
        }
        {
            int kr = tid >> 3, c8 = (tid & 7) * 8;
            float4 v0 = *reinterpret_cast<const float4*>(&g_W2[(k0 + kr) * C2 + c8]);
            float4 v1 = *reinterpret_cast<const float4*>(&g_W2[(k0 + kr) * C2 + c8 + 4]);
            *reinterpret_cast<float4*>(&sB[kr * 64 + c8])     = v0;
            *reinterpret_cast<float4*>(&sB[kr * 64 + c8 + 4]) = v1;
        }
        __syncthreads();
        #pragma unroll 8
        for (int k = 0; k < 32; k++) {
            unsigned long long a[4];
            #pragma unroll
            for (int p = 0; p < 4; p++)
                a[p] = *reinterpret_cast<const unsigned long long*>(&sA[k * 130 + ty * 8 + p * 2]);
            float4 b = *reinterpret_cast<const float4*>(&sB[k * 64 + tx * 4]);
            float bb[4] = {b.x, b.y, b.z, b.w};
            #pragma unroll
            for (int j = 0; j < 4; j++) {
                unsigned long long bp = pk2(bb[j], bb[j]);
                #pragma unroll
                for (int p = 0; p < 4; p++) acc2[p][j] = fma2(a[p], bp, acc2[p][j]);
            }
        }
        __syncthreads();
    }
    // epilogue: relu(acc+bias2) into sX2
    float* sX2 = smu;
    #pragma unroll
    for (int p = 0; p < 4; p++)
        #pragma unroll
        for (int j = 0; j < 4; j++) {
            float v0, v1;
            upk2(acc2[p][j], v0, v1);
            int c = tx * 4 + j;
            float bs = bias2[c];
            int r0 = ty * 8 + p * 2;
            sX2[r0 * 68 + c]       = fmaxf(v0 + bs, 0.f);
            sX2[(r0 + 1) * 68 + c] = fmaxf(v1 + bs, 0.f);
        }
    __syncthreads();
    // XW = X2 @ gcn_W : 128x32 outputs, 16 per thread
    #pragma unroll
    for (int i = 0; i < 16; i++) {
        int o = tid + i * 256;
        int row = o >> 5, c3 = o & 31;
        float a = 0.f;
        #pragma unroll 8
        for (int c2 = 0; c2 < C2; c2++)
            a += sX2[row * 68 + c2] * sW[c2 * C3 + c3];
        g_XW[(nb + row) * C3 + c3] = a;
    }
}

// ---------------- GCN weighted scatter (includes self loops) -----------------
__global__ void k_gcn_edge(const int* __restrict__ gsrc, const int* __restrict__ gtgt,
                           const float* __restrict__ gw) {
    int wid = (blockIdx.x * blockDim.x + threadIdx.x) >> 5;
    int lane = threadIdx.x & 31;
    if (wid >= EN_EDGES) return;
    int s = gsrc[wid], t = gtgt[wid];
    float w = gw[wid];
    atomicAdd(&g_ACC3[t * C3 + lane], w * g_XW[s * C3 + lane]);
}

// ---------------- relu + bias + global sum pool ------------------------------
__global__ void k_pool(const int* __restrict__ seg, const float* __restrict__ gcn_b,
                       float* __restrict__ out) {
    int idx = blockIdx.x * blockDim.x + threadIdx.x;
    if (idx >= N_NODES * C3) return;
    int n = idx >> 5, c = idx & 31;
    float v = fmaxf(g_ACC3[idx] + gcn_b[c], 0.f);
    atomicAdd(&out[seg[n] * C3 + c], v);
}

// =============================================================================
extern "C" void kernel_launch(void* const* d_in, const int* in_sizes, int n_in,
                              void* d_out, int out_size) {
    const float* x       = (const float*)d_in[0];
    const float* e       = (const float*)d_in[1];
    const int*   src     = (const int*)d_in[2];
    const int*   tgt     = (const int*)d_in[3];
    const int*   seg     = (const int*)d_in[4];
    const int*   gsrc    = (const int*)d_in[5];
    const int*   gtgt    = (const int*)d_in[6];
    const float* gw      = (const float*)d_in[7];
    const float* e1_w0   = (const float*)d_in[8];
    const float* e1_b0   = (const float*)d_in[9];
    const float* e1_w1   = (const float*)d_in[10];
    const float* e1_b1   = (const float*)d_in[11];
    const float* e1_wk   = (const float*)d_in[12];
    const float* e1_bk   = (const float*)d_in[13];
    const float* e1_root = (const float*)d_in[14];
    const float* e1_bias = (const float*)d_in[15];
    const float* e2_w0   = (const float*)d_in[16];
    const float* e2_b0   = (const float*)d_in[17];
    const float* e2_w1   = (const float*)d_in[18];
    const float* e2_b1   = (const float*)d_in[19];
    const float* e2_wk   = (const float*)d_in[20];
    const float* e2_bk   = (const float*)d_in[21];
    const float* e2_root = (const float*)d_in[22];
    const float* e2_bias = (const float*)d_in[23];
    const float* gcn_W   = (const float*)d_in[24];
    const float* gcn_b   = (const float*)d_in[25];
    float* out = (float*)d_out;

    k_zero<<<(N_NODES * C3 + 255) / 256, 256>>>(out, out_size);
    k_wasm<<<(K2 * C2 + 255) / 256, 256>>>(e1_wk, e1_bk, e1_root, e2_wk, e2_bk, e2_root);

    // edge MLPs + tgt-degree histogram
    k_edge_mlp<<<N_EDGES / 256, 256>>>(e, tgt, e1_w0, e1_b0, e1_w1, e1_b1,
                                          e2_w0, e2_b0, e2_w1, e2_b1);
    // CSR by tgt
    k_scan<<<1, 1024>>>();
    k_scatter<<<(N_EDGES + 255) / 256, 256>>>(tgt);

    // ECC1: edge outer-products then fused GEMM (wk+bk+root+bias+relu)
    k_p1<<<(N_NODES * 32) / 256, 256>>>(x, src);
    k_gemm1<<<N_NODES / 128, 256>>>(e1_bias);

    // ECC2: same, with fused xw = X2 @ gcn_W epilogue
    k_p2<<<(N_NODES * 32) / 256, 256>>>(src);
    k_gemm2<<<N_NODES / 128, 256>>>(e2_bias, gcn_W);

    // GCN aggregation + pool
    k_gcn_edge<<<(EN_EDGES * 32 + 255) / 256, 256>>>(gsrc, gtgt, gw);
    k_pool<<<(N_NODES * C3) / 256, 256>>>(seg, gcn_b, out);
}

// round 6
// speedup vs baseline: 1.0982x; 1.0982x over previous
#include <cuda_runtime.h>

#define N_NODES 16384
#define N_EDGES 131072
#define F_IN 6
#define S_DIM 4
#define G_NUM 256
#define H_DIM 30
#define C1 32
#define C2 64
#define C3 32
#define EN_EDGES (N_EDGES + N_NODES)
#define K1 192          /* 30*6 wk1 + 6 bk1 + 6 root1 */
#define K2 1024         /* 30*32 wk2 + 32 bk2 + 32 root2 */

// ---------------- scratch ----------------------------------------------------
__device__ float g_H1[N_EDGES * H_DIM];
__device__ float g_H2[N_EDGES * H_DIM];
__device__ float g_P1[N_NODES * K1];
__device__ float g_P2[N_NODES * K2];
__device__ float g_X1[N_NODES * C1];
__device__ float g_XW[N_NODES * C3];
__device__ float g_W1[K1 * C1];
__device__ float g_W2[K2 * C2];
__device__ int g_deg[N_NODES];
__device__ int g_rowptr[N_NODES + 1];
__device__ int g_cursor[N_NODES];
__device__ int g_csr[N_EDGES];
__device__ int g_bsum[64];
__device__ int g_boff[64];

// ---------------- packed f32x2 helpers ---------------------------------------
__device__ __forceinline__ unsigned long long pk2(float lo, float hi) {
    unsigned long long r;
    asm("mov.b64 %0, {%1, %2};" : "=l"(r) : "f"(lo), "f"(hi));
    return r;
}
__device__ __forceinline__ void upk2(unsigned long long v, float& lo, float& hi) {
    asm("mov.b64 {%0, %1}, %2;" : "=f"(lo), "=f"(hi) : "l"(v));
}
__device__ __forceinline__ unsigned long long fma2(unsigned long long a,
                                                   unsigned long long b,
                                                   unsigned long long c) {
    unsigned long long d;
    asm("fma.rn.f32x2 %0, %1, %2, %3;" : "=l"(d) : "l"(a), "l"(b), "l"(c));
    return d;
}

// ---------------- zero + weight assembly (merged) ----------------------------
__global__ void k_prep(float* __restrict__ out, int out_n,
                       const float* __restrict__ e1_wk, const float* __restrict__ e1_bk,
                       const float* __restrict__ e1_root,
                       const float* __restrict__ e2_wk, const float* __restrict__ e2_bk,
                       const float* __restrict__ e2_root) {
    int i = blockIdx.x * blockDim.x + threadIdx.x;
    if (i < N_NODES) g_deg[i] = 0;
    if (i < out_n)   out[i]   = 0.f;
    if (i < K1 * C1) {
        int k = i / C1, c = i % C1;
        float v;
        if (k < 180)      { int h = k / 6, f = k % 6; v = e1_wk[h * (F_IN * C1) + f * C1 + c]; }
        else if (k < 186) { int f = k - 180;          v = e1_bk[f * C1 + c]; }
        else              { int f = k - 186;          v = e1_root[f * C1 + c]; }
        g_W1[i] = v;
    }
    if (i < K2 * C2) {
        int k = i / C2, c = i % C2;
        float v;
        if (k < 960)      { int h = k >> 5, c1 = k & 31; v = e2_wk[h * (C1 * C2) + c1 * C2 + c]; }
        else if (k < 992) { int c1 = k - 960;            v = e2_bk[c1 * C2 + c]; }
        else              { int c1 = k - 992;            v = e2_root[c1 * C2 + c]; }
        g_W2[i] = v;
    }
}

// ---------------- parallel CSR scan (3 phases) -------------------------------
__global__ void k_scan1() {   // 64 blocks x 256: local exclusive scan
    __shared__ int sh[256];
    int tid = threadIdx.x;
    int i = blockIdx.x * 256 + tid;
    int v = g_deg[i];
    sh[tid] = v;
    __syncthreads();
    int sum = v;
    for (int d = 1; d < 256; d <<= 1) {
        int t = (tid >= d) ? sh[tid - d] : 0;
        __syncthreads();
        sum += t;
        sh[tid] = sum;
        __syncthreads();
    }
    g_rowptr[i] = sum - v;              // block-local exclusive
    if (tid == 255) g_bsum[blockIdx.x] = sum;
}

__global__ void k_scan2() {   // 1 block, 64 threads: scan block sums
    __shared__ int sh[64];
    int tid = threadIdx.x;
    int v = g_bsum[tid];
    sh[tid] = v;
    __syncthreads();
    int sum = v;
    for (int d = 1; d < 64; d <<= 1) {
        int t = (tid >= d) ? sh[tid - d] : 0;
        __syncthreads();
        sum += t;
        sh[tid] = sum;
        __syncthreads();
    }
    g_boff[tid] = sum - v;              // exclusive
}

__global__ void k_scan3() {   // add offsets, init cursor
    int i = blockIdx.x * blockDim.x + threadIdx.x;
    if (i < N_NODES) {
        int r = g_rowptr[i] + g_boff[i >> 8];
        g_rowptr[i] = r;
        g_cursor[i] = r;
        if (i == 0) g_rowptr[N_NODES] = N_EDGES;
    }
}

__global__ void k_scatter(const int* __restrict__ tgt) {
    int e = blockIdx.x * blockDim.x + threadIdx.x;
    if (e < N_EDGES) {
        int p = atomicAdd(&g_cursor[tgt[e]], 1);
        g_csr[p] = e;
    }
}

// ---------------- edge MLPs (+ tgt histogram), f32x2 -------------------------
__global__ void k_edge_mlp(const float* __restrict__ e, const int* __restrict__ tgt,
                           const float* __restrict__ w0a, const float* __restrict__ b0a,
                           const float* __restrict__ w1a, const float* __restrict__ b1a,
                           const float* __restrict__ w0b, const float* __restrict__ b0b,
                           const float* __restrict__ w1b, const float* __restrict__ b1b) {
    __shared__ float sw0[2][S_DIM * H_DIM];
    __shared__ float sb0[2][H_DIM];
    __shared__ float sw1[2][H_DIM * H_DIM];
    __shared__ float sb1[2][H_DIM];
    for (int i = threadIdx.x; i < S_DIM * H_DIM; i += blockDim.x) {
        sw0[0][i] = w0a[i]; sw0[1][i] = w0b[i];
    }
    for (int i = threadIdx.x; i < H_DIM; i += blockDim.x) {
        sb0[0][i] = b0a[i]; sb0[1][i] = b0b[i];
        sb1[0][i] = b1a[i]; sb1[1][i] = b1b[i];
    }
    for (int i = threadIdx.x; i < H_DIM * H_DIM; i += blockDim.x) {
        sw1[0][i] = w1a[i]; sw1[1][i] = w1b[i];
    }
    __syncthreads();

    int eid = blockIdx.x * blockDim.x + threadIdx.x;
    if (eid >= N_EDGES) return;
    atomicAdd(&g_deg[tgt[eid]], 1);
    float4 ev4 = *reinterpret_cast<const float4*>(e + eid * 4);
    float ev[4] = {ev4.x, ev4.y, ev4.z, ev4.w};

    #pragma unroll
    for (int set = 0; set < 2; set++) {
        // layer 0: 15 pair-accumulators over j
        unsigned long long h0p[15];
        #pragma unroll
        for (int j = 0; j < 15; j++)
            h0p[j] = *reinterpret_cast<const unsigned long long*>(&sb0[set][2 * j]);
        #pragma unroll
        for (int s = 0; s < S_DIM; s++) {
            unsigned long long ep = pk2(ev[s], ev[s]);
            #pragma unroll
            for (int j = 0; j < 15; j++) {
                unsigned long long wp =
                    *reinterpret_cast<const unsigned long long*>(&sw0[set][s * H_DIM + 2 * j]);
                h0p[j] = fma2(wp, ep, h0p[j]);
            }
        }
        float h0[H_DIM];
        #pragma unroll
        for (int j = 0; j < 15; j++) {
            float a, b;
            upk2(h0p[j], a, b);
            h0[2 * j] = fmaxf(a, 0.f);
            h0[2 * j + 1] = fmaxf(b, 0.f);
        }
        // layer 1: 15 pair-accumulators over j, 30 k-steps
        unsigned long long h1p[15];
        #pragma unroll
        for (int j = 0; j < 15; j++)
            h1p[j] = *reinterpret_cast<const unsigned long long*>(&sb1[set][2 * j]);
        #pragma unroll 6
        for (int k = 0; k < H_DIM; k++) {
            unsigned long long hp = pk2(h0[k], h0[k]);
            #pragma unroll
            for (int j = 0; j < 15; j++) {
                unsigned long long wp =
                    *reinterpret_cast<const unsigned long long*>(&sw1[set][k * H_DIM + 2 * j]);
                h1p[j] = fma2(wp, hp, h1p[j]);
            }
        }
        float* dst = (set == 0 ? g_H1 : g_H2) + eid * H_DIM;
        #pragma unroll
        for (int j = 0; j < 15; j++) {
            float a, b;
            upk2(h1p[j], a, b);
            dst[2 * j] = fmaxf(a, 0.f);
            dst[2 * j + 1] = fmaxf(b, 0.f);
        }
    }
}

// ---------------- P1: per-target outer-product sums (ECC1) -------------------
__global__ void k_p1(const float* __restrict__ x, const int* __restrict__ src) {
    int t = (blockIdx.x * blockDim.x + threadIdx.x) >> 5;
    int lane = threadIdx.x & 31;
    if (t >= N_NODES) return;
    int rs = g_rowptr[t], re = g_rowptr[t + 1];
    float acc[6] = {0.f, 0.f, 0.f, 0.f, 0.f, 0.f};
    float hv_fix = (lane == 30) ? 1.f : 0.f;
    for (int pos = rs; pos < re; pos++) {
        int eid = g_csr[pos];
        int s = src[eid];
        float xl = (lane < 6) ? x[s * 6 + lane] : 0.f;
        float hv = (lane < 30) ? g_H1[eid * H_DIM + lane] : hv_fix;
        #pragma unroll
        for (int f = 0; f < 6; f++)
            acc[f] += hv * __shfl_sync(0xffffffffu, xl, f);
    }
    if (lane == 31) {
        #pragma unroll
        for (int f = 0; f < 6; f++) acc[f] = x[t * 6 + f];
    }
    #pragma unroll
    for (int f = 0; f < 6; f++) g_P1[t * K1 + lane * 6 + f] = acc[f];
}

// ---------------- GEMM1: X1 = relu(P1 @ W1 + bias1) --------------------------
__global__ void k_gemm1(const float* __restrict__ bias1) {
    __shared__ float sA[32 * 130];
    __shared__ float sB[32 * 32];
    int tid = threadIdx.x;
    int nb = blockIdx.x * 128;
    int tx = tid & 7;
    int ty = tid >> 3;
    unsigned long long acc2[2][4];
    #pragma unroll
    for (int p = 0; p < 2; p++)
        #pragma unroll
        for (int j = 0; j < 4; j++) acc2[p][j] = 0ull;

    for (int k0 = 0; k0 < K1; k0 += 32) {
        int lrow = tid >> 3, lk4 = (tid & 7) * 4;
        #pragma unroll
        for (int j = 0; j < 4; j++) {
            int row = lrow + 32 * j;
            float4 v = *reinterpret_cast<const float4*>(&g_P1[(nb + row) * K1 + k0 + lk4]);
            sA[(lk4 + 0) * 130 + row] = v.x;
            sA[(lk4 + 1) * 130 + row] = v.y;
            sA[(lk4 + 2) * 130 + row] = v.z;
            sA[(lk4 + 3) * 130 + row] = v.w;
        }
        {
            int kr = tid >> 3, c4 = (tid & 7) * 4;
            float4 v = *reinterpret_cast<const float4*>(&g_W1[(k0 + kr) * C1 + c4]);
            *reinterpret_cast<float4*>(&sB[kr * 32 + c4]) = v;
        }
        __syncthreads();
        #pragma unroll 8
        for (int k = 0; k < 32; k++) {
            unsigned long long a0 = *reinterpret_cast<const unsigned long long*>(&sA[k * 130 + ty * 4]);
            unsigned long long a1 = *reinterpret_cast<const unsigned long long*>(&sA[k * 130 + ty * 4 + 2]);
            float4 b = *reinterpret_cast<const float4*>(&sB[k * 32 + tx * 4]);
            float bb[4] = {b.x, b.y, b.z, b.w};
            #pragma unroll
            for (int j = 0; j < 4; j++) {
                unsigned long long bp = pk2(bb[j], bb[j]);
                acc2[0][j] = fma2(a0, bp, acc2[0][j]);
                acc2[1][j] = fma2(a1, bp, acc2[1][j]);
            }
        }
        __syncthreads();
    }
    #pragma unroll
    for (int p = 0; p < 2; p++)
        #pragma unroll
        for (int j = 0; j < 4; j++) {
            float v0, v1;
            upk2(acc2[p][j], v0, v1);
            int c = tx * 4 + j;
            float bs = bias1[c];
            int r0 = nb + ty * 4 + p * 2;
            g_X1[r0 * C1 + c]       = fmaxf(v0 + bs, 0.f);
            g_X1[(r0 + 1) * C1 + c] = fmaxf(v1 + bs, 0.f);
        }
}

// ---------------- P2: per-target outer-product sums (ECC2) -------------------
__global__ void k_p2(const int* __restrict__ src) {
    int t = (blockIdx.x * blockDim.x + threadIdx.x) >> 5;
    int lane = threadIdx.x & 31;
    if (t >= N_NODES) return;
    int rs = g_rowptr[t], re = g_rowptr[t + 1];
    float acc[31];
    #pragma unroll
    for (int h = 0; h < 31; h++) acc[h] = 0.f;
    for (int pos = rs; pos < re; pos++) {
        int eid = g_csr[pos];
        int s = src[eid];
        float x1v = g_X1[s * C1 + lane];
        float hl = (lane < 30) ? g_H2[eid * H_DIM + lane] : 0.f;
        #pragma unroll
        for (int h = 0; h < 30; h++)
            acc[h] += __shfl_sync(0xffffffffu, hl, h) * x1v;
        acc[30] += x1v;
    }
    #pragma unroll
    for (int h = 0; h < 31; h++)
        g_P2[t * K2 + h * 32 + lane] = acc[h];
    g_P2[t * K2 + 992 + lane] = g_X1[t * C1 + lane];
}

// ---------------- GEMM2 + fused GCN-xw ---------------------------------------
__global__ void k_gemm2(const float* __restrict__ bias2, const float* __restrict__ gcnW) {
    __shared__ float smu[128 * 68];
    __shared__ float sW[C2 * C3];
    float* sA = smu;
    float* sB = smu + 4160;
    int tid = threadIdx.x;
    int nb = blockIdx.x * 128;
    for (int i = tid; i < C2 * C3; i += 256) sW[i] = gcnW[i];

    int tx = tid & 15;
    int ty = tid >> 4;
    unsigned long long acc2[4][4];
    #pragma unroll
    for (int p = 0; p < 4; p++)
        #pragma unroll
        for (int j = 0; j < 4; j++) acc2[p][j] = 0ull;

    for (int k0 = 0; k0 < K2; k0 += 32) {
        int lrow = tid >> 3, lk4 = (tid & 7) * 4;
        #pragma unroll
        for (int j = 0; j < 4; j++) {
            int row = lrow + 32 * j;
            float4 v = *reinterpret_cast<const float4*>(&g_P2[(nb + row) * K2 + k0 + lk4]);
            sA[(lk4 + 0) * 130 + row] = v.x;
            sA[(lk4 + 1) * 130 + row] = v.y;
            sA[(lk4 + 2) * 130 + row] = v.z;
            sA[(lk4 + 3) * 130 + row] = v.w;
        }
        {
            int kr = tid >> 3, c8 = (tid & 7) * 8;
            float4 v0 = *reinterpret_cast<const float4*>(&g_W2[(k0 + kr) * C2 + c8]);
            float4 v1 = *reinterpret_cast<const float4*>(&g_W2[(k0 + kr) * C2 + c8 + 4]);
            *reinterpret_cast<float4*>(&sB[kr * 64 + c8])     = v0;
            *reinterpret_cast<float4*>(&sB[kr * 64 + c8 + 4]) = v1;
        }
        __syncthreads();
        #pragma unroll 8
        for (int k = 0; k < 32; k++) {
            unsigned long long a[4];
            #pragma unroll
            for (int p = 0; p < 4; p++)
                a[p] = *reinterpret_cast<const unsigned long long*>(&sA[k * 130 + ty * 8 + p * 2]);
            float4 b = *reinterpret_cast<const float4*>(&sB[k * 64 + tx * 4]);
            float bb[4] = {b.x, b.y, b.z, b.w};
            #pragma unroll
            for (int j = 0; j < 4; j++) {
                unsigned long long bp = pk2(bb[j], bb[j]);
                #pragma unroll
                for (int p = 0; p < 4; p++) acc2[p][j] = fma2(a[p], bp, acc2[p][j]);
            }
        }
        __syncthreads();
    }
    float* sX2 = smu;
    #pragma unroll
    for (int p = 0; p < 4; p++)
        #pragma unroll
        for (int j = 0; j < 4; j++) {
            float v0, v1;
            upk2(acc2[p][j], v0, v1);
            int c = tx * 4 + j;
            float bs = bias2[c];
            int r0 = ty * 8 + p * 2;
            sX2[r0 * 68 + c]       = fmaxf(v0 + bs, 0.f);
            sX2[(r0 + 1) * 68 + c] = fmaxf(v1 + bs, 0.f);
        }
    __syncthreads();
    #pragma unroll
    for (int i = 0; i < 16; i++) {
        int o = tid + i * 256;
        int row = o >> 5, c3 = o & 31;
        float a = 0.f;
        #pragma unroll 8
        for (int c2 = 0; c2 < C2; c2++)
            a += sX2[row * 68 + c2] * sW[c2 * C3 + c3];
        g_XW[(nb + row) * C3 + c3] = a;
    }
}

// ---------------- GCN aggregation + bias + relu + pool (CSR reuse, no atomics
//                  on nodes; only G_NUM*32 pool atomics) ----------------------
__global__ void k_gcn(const int* __restrict__ src, const float* __restrict__ gw,
                      const int* __restrict__ seg, const float* __restrict__ gcn_b,
                      float* __restrict__ out) {
    int t = (blockIdx.x * blockDim.x + threadIdx.x) >> 5;
    int lane = threadIdx.x & 31;
    if (t >= N_NODES) return;
    int rs = g_rowptr[t], re = g_rowptr[t + 1];
    // self loop: gcn edge index E + t
    float acc = gw[N_EDGES + t] * g_XW[t * C3 + lane];
    for (int pos = rs; pos < re; pos++) {
        int eid = g_csr[pos];
        int s = src[eid];
        acc += gw[eid] * g_XW[s * C3 + lane];
    }
    float v = fmaxf(acc + gcn_b[lane], 0.f);
    atomicAdd(&out[seg[t] * C3 + lane], v);
}

// =============================================================================
extern "C" void kernel_launch(void* const* d_in, const int* in_sizes, int n_in,
                              void* d_out, int out_size) {
    const float* x       = (const float*)d_in[0];
    const float* e       = (const float*)d_in[1];
    const int*   src     = (const int*)d_in[2];
    const int*   tgt     = (const int*)d_in[3];
    const int*   seg     = (const int*)d_in[4];
    const float* gw      = (const float*)d_in[7];
    const float* e1_w0   = (const float*)d_in[8];
    const float* e1_b0   = (const float*)d_in[9];
    const float* e1_w1   = (const float*)d_in[10];
    const float* e1_b1   = (const float*)d_in[11];
    const float* e1_wk   = (const float*)d_in[12];
    const float* e1_bk   = (const float*)d_in[13];
    const float* e1_root = (const float*)d_in[14];
    const float* e1_bias = (const float*)d_in[15];
    const float* e2_w0   = (const float*)d_in[16];
    const float* e2_b0   = (const float*)d_in[17];
    const float* e2_w1   = (const float*)d_in[18];
    const float* e2_b1   = (const float*)d_in[19];
    const float* e2_wk   = (const float*)d_in[20];
    const float* e2_bk   = (const float*)d_in[21];
    const float* e2_root = (const float*)d_in[22];
    const float* e2_bias = (const float*)d_in[23];
    const float* gcn_W   = (const float*)d_in[24];
    const float* gcn_b   = (const float*)d_in[25];
    float* out = (float*)d_out;

    // zero + weight assembly (one kernel)
    k_prep<<<(K2 * C2 + 255) / 256, 256>>>(out, out_size,
                                           e1_wk, e1_bk, e1_root, e2_wk, e2_bk, e2_root);

    // edge MLPs + tgt-degree histogram
    k_edge_mlp<<<N_EDGES / 256, 256>>>(e, tgt, e1_w0, e1_b0, e1_w1, e1_b1,
                                          e2_w0, e2_b0, e2_w1, e2_b1);

    // parallel CSR build by tgt
    k_scan1<<<64, 256>>>();
    k_scan2<<<1, 64>>>();
    k_scan3<<<N_NODES / 256, 256>>>();
    k_scatter<<<(N_EDGES + 255) / 256, 256>>>(tgt);

    // ECC1
    k_p1<<<(N_NODES * 32) / 256, 256>>>(x, src);
    k_gemm1<<<N_NODES / 128, 256>>>(e1_bias);

    // ECC2 (+ fused xw epilogue)
    k_p2<<<(N_NODES * 32) / 256, 256>>>(src);
    k_gemm2<<<N_NODES / 128, 256>>>(e2_bias, gcn_W);

    // GCN aggregation + bias + relu + pool (CSR reuse)
    k_gcn<<<(N_NODES * 32) / 256, 256>>>(src, gw, seg, gcn_b, out);
}

// round 9
// speedup vs baseline: 1.4906x; 1.3573x over previous
#include <cuda_runtime.h>

#define N_NODES 16384
#define N_EDGES 131072
#define F_IN 6
#define S_DIM 4
#define G_NUM 256
#define H_DIM 30
#define C1 32
#define C2 64
#define C3 32
#define K1 192          /* 30*6 wk1 + 6 bk1 + 6 root1 */
#define K2 1024         /* 30*32 wk2 + 32 bk2 + 32 root2 */

// ---------------- scratch ----------------------------------------------------
__device__ float g_H1[N_EDGES * H_DIM];
__device__ float g_H2[N_EDGES * H_DIM];
__device__ float g_P2[N_NODES * K2];
__device__ float g_X1[N_NODES * C1];
__device__ float g_XW[N_NODES * C3];
__device__ float g_W1[K1 * C1];
__device__ float g_W2[K2 * C2];
__device__ int g_deg[N_NODES];          // zero at start of each call (see k_gcn tail)
__device__ int g_rowptr[N_NODES + 1];
__device__ int g_cursor[N_NODES];
__device__ int g_csr[N_EDGES];
__device__ int g_chainflag[65];         // prefix+1; 0 = not ready
__device__ int g_done;

// ---------------- packed f32x2 helpers ---------------------------------------
__device__ __forceinline__ unsigned long long pk2(float lo, float hi) {
    unsigned long long r;
    asm("mov.b64 %0, {%1, %2};" : "=l"(r) : "f"(lo), "f"(hi));
    return r;
}
__device__ __forceinline__ void upk2(unsigned long long v, float& lo, float& hi) {
    asm("mov.b64 {%0, %1}, %2;" : "=f"(lo), "=f"(hi) : "l"(v));
}
__device__ __forceinline__ unsigned long long fma2(unsigned long long a,
                                                   unsigned long long b,
                                                   unsigned long long c) {
    unsigned long long d;
    asm("fma.rn.f32x2 %0, %1, %2, %3;" : "=l"(d) : "l"(a), "l"(b), "l"(c));
    return d;
}

// ---------------- kernel 1: edge MLPs + tgt hist + prep (merged) -------------
__global__ void k_mlp(const float* __restrict__ e, const int* __restrict__ tgt,
                      const float* __restrict__ w0a, const float* __restrict__ b0a,
                      const float* __restrict__ w1a, const float* __restrict__ b1a,
                      const float* __restrict__ w0b, const float* __restrict__ b0b,
                      const float* __restrict__ w1b, const float* __restrict__ b1b,
                      float* __restrict__ out, int out_n,
                      const float* __restrict__ e1_wk, const float* __restrict__ e1_bk,
                      const float* __restrict__ e1_root,
                      const float* __restrict__ e2_wk, const float* __restrict__ e2_bk,
                      const float* __restrict__ e2_root) {
    __shared__ float sw0[2][S_DIM * H_DIM];
    __shared__ float sb0[2][H_DIM];
    __shared__ float sw1[2][H_DIM * H_DIM];
    __shared__ float sb1[2][H_DIM];
    for (int i = threadIdx.x; i < S_DIM * H_DIM; i += blockDim.x) {
        sw0[0][i] = w0a[i]; sw0[1][i] = w0b[i];
    }
    for (int i = threadIdx.x; i < H_DIM; i += blockDim.x) {
        sb0[0][i] = b0a[i]; sb0[1][i] = b0b[i];
        sb1[0][i] = b1a[i]; sb1[1][i] = b1b[i];
    }
    for (int i = threadIdx.x; i < H_DIM * H_DIM; i += blockDim.x) {
        sw1[0][i] = w1a[i]; sw1[1][i] = w1b[i];
    }
    __syncthreads();

    int eid = blockIdx.x * blockDim.x + threadIdx.x;
    if (eid >= N_EDGES) return;

    // ---- prep duties spread over the grid ----
    if (eid < out_n) out[eid] = 0.f;
    if (eid < K1 * C1) {
        int k = eid / C1, c = eid % C1;
        float v;
        if (k < 180)      { int h = k / 6, f = k % 6; v = e1_wk[h * (F_IN * C1) + f * C1 + c]; }
        else if (k < 186) { int f = k - 180;          v = e1_bk[f * C1 + c]; }
        else              { int f = k - 186;          v = e1_root[f * C1 + c]; }
        g_W1[eid] = v;
    }
    if (eid < K2 * C2) {
        int k = eid / C2, c = eid % C2;
        float v;
        if (k < 960)      { int h = k >> 5, c1 = k & 31; v = e2_wk[h * (C1 * C2) + c1 * C2 + c]; }
        else if (k < 992) { int c1 = k - 960;            v = e2_bk[c1 * C2 + c]; }
        else              { int c1 = k - 992;            v = e2_root[c1 * C2 + c]; }
        g_W2[eid] = v;
    }

    atomicAdd(&g_deg[tgt[eid]], 1);

    float4 ev4 = *reinterpret_cast<const float4*>(e + eid * 4);
    float ev[4] = {ev4.x, ev4.y, ev4.z, ev4.w};

    #pragma unroll
    for (int set = 0; set < 2; set++) {
        unsigned long long h0p[15];
        #pragma unroll
        for (int j = 0; j < 15; j++)
            h0p[j] = *reinterpret_cast<const unsigned long long*>(&sb0[set][2 * j]);
        #pragma unroll
        for (int s = 0; s < S_DIM; s++) {
            unsigned long long ep = pk2(ev[s], ev[s]);
            #pragma unroll
            for (int j = 0; j < 15; j++) {
                unsigned long long wp =
                    *reinterpret_cast<const unsigned long long*>(&sw0[set][s * H_DIM + 2 * j]);
                h0p[j] = fma2(wp, ep, h0p[j]);
            }
        }
        float h0[H_DIM];
        #pragma unroll
        for (int j = 0; j < 15; j++) {
            float a, b;
            upk2(h0p[j], a, b);
            h0[2 * j] = fmaxf(a, 0.f);
            h0[2 * j + 1] = fmaxf(b, 0.f);
        }
        unsigned long long h1p[15];
        #pragma unroll
        for (int j = 0; j < 15; j++)
            h1p[j] = *reinterpret_cast<const unsigned long long*>(&sb1[set][2 * j]);
        #pragma unroll 6
        for (int k = 0; k < H_DIM; k++) {
            unsigned long long hp = pk2(h0[k], h0[k]);
            #pragma unroll
            for (int j = 0; j < 15; j++) {
                unsigned long long wp =
                    *reinterpret_cast<const unsigned long long*>(&sw1[set][k * H_DIM + 2 * j]);
                h1p[j] = fma2(wp, hp, h1p[j]);
            }
        }
        float* dst = (set == 0 ? g_H1 : g_H2) + eid * H_DIM;
        #pragma unroll
        for (int j = 0; j < 15; j++) {
            float a, b;
            upk2(h1p[j], a, b);
            dst[2 * j] = fmaxf(a, 0.f);
            dst[2 * j + 1] = fmaxf(b, 0.f);
        }
    }
}

// ---------------- kernel 2: full CSR build in ONE kernel ----------------------
// 64 blocks x 256 threads: local scan -> chained-lookback prefix ->
// grid barrier (done counter, all 64 blocks resident) -> scatter.
__global__ void k_csr(const int* __restrict__ tgt) {
    __shared__ int sh[256];
    __shared__ int s_prefix;
    int tid = threadIdx.x, b = blockIdx.x;
    int i = b * 256 + tid;
    int v = g_deg[i];
    sh[tid] = v;
    __syncthreads();
    int sum = v;
    for (int d = 1; d < 256; d <<= 1) {
        int t = (tid >= d) ? sh[tid - d] : 0;
        __syncthreads();
        sum += t;
        sh[tid] = sum;
        __syncthreads();
    }
    if (tid == 0) {
        int p = 0;
        if (b > 0) {
            while ((p = atomicAdd(&g_chainflag[b], 0)) == 0) {}
            p -= 1;
        }
        s_prefix = p;
        atomicExch(&g_chainflag[b + 1], p + sh[255] + 1);
    }
    __syncthreads();
    int r = s_prefix + sum - v;         // global exclusive prefix
    g_rowptr[i] = r;
    g_cursor[i] = r;
    if (b == 63 && tid == 255) g_rowptr[N_NODES] = N_EDGES;
    __threadfence();
    __syncthreads();
    if (tid == 0) atomicAdd(&g_done, 1);
    if (tid == 0) { while (atomicAdd(&g_done, 0) < 64) {} }
    __syncthreads();
    // scatter this block's slice of edges
    for (int e = b * 2048 + tid; e < (b + 1) * 2048; e += 256) {
        int p = atomicAdd(&g_cursor[tgt[e]], 1);
        g_csr[p] = e;
    }
}

// ---------------- kernel 3: fused ECC1 (P1 rows in smem + mini-GEMM) ---------
// block = 256 threads = 8 warps = 8 targets
__global__ void k_ecc1(const float* __restrict__ x, const int* __restrict__ src,
                       const float* __restrict__ bias1) {
    __shared__ float sW1[K1 * C1];      // 24 KB
    __shared__ float sP1[8][K1];        // 6 KB
    int tid = threadIdx.x;
    int w = tid >> 5, lane = tid & 31;
    int t = blockIdx.x * 8 + w;
    // cooperative W1 load
    for (int i = tid; i < K1 * C1 / 4; i += 256)
        ((float4*)sW1)[i] = ((const float4*)g_W1)[i];

    // phase A: P1 row for this warp's target (lane = k-row: 0..29 wk, 30 bk, 31 root)
    int rs = g_rowptr[t], re = g_rowptr[t + 1];
    float acc[6] = {0.f, 0.f, 0.f, 0.f, 0.f, 0.f};
    float hv_fix = (lane == 30) ? 1.f : 0.f;
    int pos = rs;
    int eid = 0, s = 0;
    if (pos < re) { eid = g_csr[pos]; s = src[eid]; }
    while (pos < re) {
        float xl = (lane < 6) ? x[s * 6 + lane] : 0.f;
        float hv = (lane < 30) ? g_H1[eid * H_DIM + lane] : hv_fix;
        int pos2 = pos + 1;
        int eid2 = 0, s2 = 0;
        if (pos2 < re) { eid2 = g_csr[pos2]; s2 = src[eid2]; }
        #pragma unroll
        for (int f = 0; f < 6; f++)
            acc[f] += hv * __shfl_sync(0xffffffffu, xl, f);
        pos = pos2; eid = eid2; s = s2;
    }
    if (lane == 31) {
        #pragma unroll
        for (int f = 0; f < 6; f++) acc[f] = x[t * 6 + f];
    }
    #pragma unroll
    for (int f = 0; f < 6; f++) sP1[w][lane * 6 + f] = acc[f];
    __syncthreads();

    // phase B: X1[t, lane] = relu(sP1[w,:] @ W1[:, lane] + bias1[lane])
    float av = bias1[lane];
    const float* pr = sP1[w];
    #pragma unroll 8
    for (int k = 0; k < K1; k += 4) {
        float4 p = *reinterpret_cast<const float4*>(pr + k);
        av += p.x * sW1[(k + 0) * C1 + lane];
        av += p.y * sW1[(k + 1) * C1 + lane];
        av += p.z * sW1[(k + 2) * C1 + lane];
        av += p.w * sW1[(k + 3) * C1 + lane];
    }
    g_X1[t * C1 + lane] = fmaxf(av, 0.f);
}

// ---------------- kernel 4: P2 per-target outer-product sums -----------------
__global__ void k_p2(const int* __restrict__ src) {
    int t = (blockIdx.x * blockDim.x + threadIdx.x) >> 5;
    int lane = threadIdx.x & 31;
    if (t >= N_NODES) return;
    int rs = g_rowptr[t], re = g_rowptr[t + 1];
    float acc[31];
    #pragma unroll
    for (int h = 0; h < 31; h++) acc[h] = 0.f;
    int pos = rs;
    int eid = 0, s = 0;
    if (pos < re) { eid = g_csr[pos]; s = src[eid]; }
    while (pos < re) {
        float x1v = g_X1[s * C1 + lane];
        float hl = (lane < 30) ? g_H2[eid * H_DIM + lane] : 0.f;
        int pos2 = pos + 1;
        int eid2 = 0, s2 = 0;
        if (pos2 < re) { eid2 = g_csr[pos2]; s2 = src[eid2]; }
        #pragma unroll
        for (int h = 0; h < 30; h++)
            acc[h] += __shfl_sync(0xffffffffu, hl, h) * x1v;
        acc[30] += x1v;
        pos = pos2; eid = eid2; s = s2;
    }
    #pragma unroll
    for (int h = 0; h < 31; h++)
        g_P2[t * K2 + h * 32 + lane] = acc[h];
    g_P2[t * K2 + 992 + lane] = g_X1[t * C1 + lane];
}

// ---------------- kernel 5: GEMM2 + fused GCN-xw -----------------------------
__global__ void k_gemm2(const float* __restrict__ bias2, const float* __restrict__ gcnW) {
    __shared__ float smu[128 * 68];
    __shared__ float sW[C2 * C3];
    float* sA = smu;
    float* sB = smu + 4160;
    int tid = threadIdx.x;
    int nb = blockIdx.x * 128;
    for (int i = tid; i < C2 * C3; i += 256) sW[i] = gcnW[i];

    int tx = tid & 15;
    int ty = tid >> 4;
    unsigned long long acc2[4][4];
    #pragma unroll
    for (int p = 0; p < 4; p++)
        #pragma unroll
        for (int j = 0; j < 4; j++) acc2[p][j] = 0ull;

    for (int k0 = 0; k0 < K2; k0 += 32) {
        int lrow = tid >> 3, lk4 = (tid & 7) * 4;
        #pragma unroll
        for (int j = 0; j < 4; j++) {
            int row = lrow + 32 * j;
            float4 v = *reinterpret_cast<const float4*>(&g_P2[(nb + row) * K2 + k0 + lk4]);
            sA[(lk4 + 0) * 130 + row] = v.x;
            sA[(lk4 + 1) * 130 + row] = v.y;
            sA[(lk4 + 2) * 130 + row] = v.z;
            sA[(lk4 + 3) * 130 + row] = v.w;
        }
        {
            int kr = tid >> 3, c8 = (tid & 7) * 8;
            float4 v0 = *reinterpret_cast<const float4*>(&g_W2[(k0 + kr) * C2 + c8]);
            float4 v1 = *reinterpret_cast<const float4*>(&g_W2[(k0 + kr) * C2 + c8 + 4]);
            *reinterpret_cast<float4*>(&sB[kr * 64 + c8])     = v0;
            *reinterpret_cast<float4*>(&sB[kr * 64 + c8 + 4]) = v1;
        }
        __syncthreads();
        #pragma unroll 8
        for (int k = 0; k < 32; k++) {
            unsigned long long a[4];
            #pragma unroll
            for (int p = 0; p < 4; p++)
                a[p] = *reinterpret_cast<const unsigned long long*>(&sA[k * 130 + ty * 8 + p * 2]);
            float4 b = *reinterpret_cast<const float4*>(&sB[k * 64 + tx * 4]);
            float bb[4] = {b.x, b.y, b.z, b.w};
            #pragma unroll
            for (int j = 0; j < 4; j++) {
                unsigned long long bp = pk2(bb[j], bb[j]);
                #pragma unroll
                for (int p = 0; p < 4; p++) acc2[p][j] = fma2(a[p], bp, acc2[p][j]);
            }
        }
        __syncthreads();
    }
    float* sX2 = smu;
    #pragma unroll
    for (int p = 0; p < 4; p++)
        #pragma unroll
        for (int j = 0; j < 4; j++) {
            float v0, v1;
            upk2(acc2[p][j], v0, v1);
            int c = tx * 4 + j;
            float bs = bias2[c];
            int r0 = ty * 8 + p * 2;
            sX2[r0 * 68 + c]       = fmaxf(v0 + bs, 0.f);
            sX2[(r0 + 1) * 68 + c] = fmaxf(v1 + bs, 0.f);
        }
    __syncthreads();
    #pragma unroll
    for (int i = 0; i < 16; i++) {
        int o = tid + i * 256;
        int row = o >> 5, c3 = o & 31;
        float a = 0.f;
        #pragma unroll 8
        for (int c2 = 0; c2 < C2; c2++)
            a += sX2[row * 68 + c2] * sW[c2 * C3 + c3];
        g_XW[(nb + row) * C3 + c3] = a;
    }
}

// ---------------- kernel 6: GCN agg + bias + relu + pool + state reset -------
__global__ void k_gcn(const int* __restrict__ src, const float* __restrict__ gw,
                      const int* __restrict__ seg, const float* __restrict__ gcn_b,
                      float* __restrict__ out) {
    int gthr = blockIdx.x * blockDim.x + threadIdx.x;
    int t = gthr >> 5;
    int lane = threadIdx.x & 31;
    if (t >= N_NODES) return;
    // reset per-call state for the NEXT call (this is the last kernel)
    if (lane == 0) g_deg[t] = 0;
    if (gthr < 65) g_chainflag[gthr] = 0;
    if (gthr == 65) g_done = 0;

    int rs = g_rowptr[t], re = g_rowptr[t + 1];
    float acc = gw[N_EDGES + t] * g_XW[t * C3 + lane];    // self loop
    int pos = rs;
    int eid = 0, s = 0;
    if (pos < re) { eid = g_csr[pos]; s = src[eid]; }
    while (pos < re) {
        float xv = g_XW[s * C3 + lane];
        float wv = gw[eid];
        int pos2 = pos + 1;
        int eid2 = 0, s2 = 0;
        if (pos2 < re) { eid2 = g_csr[pos2]; s2 = src[eid2]; }
        acc += wv * xv;
        pos = pos2; eid = eid2; s = s2;
    }
    float v = fmaxf(acc + gcn_b[lane], 0.f);
    atomicAdd(&out[seg[t] * C3 + lane], v);
}

// =============================================================================
extern "C" void kernel_launch(void* const* d_in, const int* in_sizes, int n_in,
                              void* d_out, int out_size) {
    const float* x       = (const float*)d_in[0];
    const float* e       = (const float*)d_in[1];
    const int*   src     = (const int*)d_in[2];
    const int*   tgt     = (const int*)d_in[3];
    const int*   seg     = (const int*)d_in[4];
    const float* gw      = (const float*)d_in[7];
    const float* e1_w0   = (const float*)d_in[8];
    const float* e1_b0   = (const float*)d_in[9];
    const float* e1_w1   = (const float*)d_in[10];
    const float* e1_b1   = (const float*)d_in[11];
    const float* e1_wk   = (const float*)d_in[12];
    const float* e1_bk   = (const float*)d_in[13];
    const float* e1_root = (const float*)d_in[14];
    const float* e1_bias = (const float*)d_in[15];
    const float* e2_w0   = (const float*)d_in[16];
    const float* e2_b0   = (const float*)d_in[17];
    const float* e2_w1   = (const float*)d_in[18];
    const float* e2_b1   = (const float*)d_in[19];
    const float* e2_wk   = (const float*)d_in[20];
    const float* e2_bk   = (const float*)d_in[21];
    const float* e2_root = (const float*)d_in[22];
    const float* e2_bias = (const float*)d_in[23];
    const float* gcn_W   = (const float*)d_in[24];
    const float* gcn_b   = (const float*)d_in[25];
    float* out = (float*)d_out;

    // 1. edge MLPs + histogram + prep (zero out, assemble W1/W2)
    k_mlp<<<N_EDGES / 256, 256>>>(e, tgt, e1_w0, e1_b0, e1_w1, e1_b1,
                                  e2_w0, e2_b0, e2_w1, e2_b1,
                                  out, out_size,
                                  e1_wk, e1_bk, e1_root, e2_wk, e2_bk, e2_root);
    // 2. CSR build (scan + scatter in one kernel, 64 resident blocks)
    k_csr<<<64, 256>>>(tgt);
    // 3. ECC1 fused (P1 in smem + mini-GEMM -> X1)
    k_ecc1<<<N_NODES / 8, 256>>>(x, src, e1_bias);
    // 4. P2 outer-product sums
    k_p2<<<(N_NODES * 32) / 256, 256>>>(src);
    // 5. GEMM2 (+bias+relu) + fused xw = X2 @ gcn_W
    k_gemm2<<<N_NODES / 128, 256>>>(e2_bias, gcn_W);
    // 6. GCN aggregation + bias + relu + pool (+ state reset for next call)
    k_gcn<<<(N_NODES * 32) / 256, 256>>>(src, gw, seg, gcn_b, out);
}